// round 11
// baseline (speedup 1.0000x reference)
#include <cuda_runtime.h>

#define ROWS 4096
#define COLS 8192
#define THREADS 512
#define NWARPS (THREADS / 32)          // 16
#define VPT (COLS / (THREADS * 4))     // 4 float4 per thread = 16 floats
#define CAP 1024                       // candidate capacity (Newton fallback beyond 32)

__device__ __forceinline__ float warp_sum(float v) {
#pragma unroll
    for (int off = 16; off; off >>= 1)
        v += __shfl_xor_sync(0xffffffffu, v, off);
    return v;
}
__device__ __forceinline__ float warp_max(float v) {
#pragma unroll
    for (int off = 16; off; off >>= 1)
        v = fmaxf(v, __shfl_xor_sync(0xffffffffu, v, off));
    return v;
}

__global__ void __launch_bounds__(THREADS, 3)
sparsemax_kernel(const float* __restrict__ x, float* __restrict__ out) {
    const int row  = blockIdx.x;
    const int t    = threadIdx.x;
    const int warp = t >> 5;
    const int lane = t & 31;

    const float4* __restrict__ x4 = reinterpret_cast<const float4*>(x + (size_t)row * COLS);
    float4*       __restrict__ o4 = reinterpret_cast<float4*>(out + (size_t)row * COLS);

    // Front-batched coalesced loads: 4 x float4 per thread (16 data regs).
    float4 v[VPT];
#pragma unroll
    for (int i = 0; i < VPT; i++) v[i] = x4[t + i * THREADS];

    __shared__ float s_max[NWARPS];
    __shared__ float s_cand[CAP];
    __shared__ int   s_n;
    __shared__ float s_tau;
    __shared__ float s_red[2][NWARPS];   // Newton fallback only

    // ---- rowmax (single block reduction) ----
    float m = v[0].x;
#pragma unroll
    for (int i = 0; i < VPT; i++)
        m = fmaxf(m, fmaxf(fmaxf(v[i].x, v[i].y), fmaxf(v[i].z, v[i].w)));
    m = warp_max(m);
    if (lane == 0) s_max[warp] = m;
    if (t == 0) s_n = 0;
    __syncthreads();
    float rowmax = s_max[0];
#pragma unroll
    for (int w = 1; w < NWARPS; w++) rowmax = fmaxf(rowmax, s_max[w]);

    // ---- candidate compaction: support(tau*) subset of {x > rowmax-1},
    //      since x_max - tau <= sum_support(x - tau) = 1  =>  tau >= rowmax - 1.
    const float lb = rowmax - 1.0f;
    float e[VPT * 4];
#pragma unroll
    for (int i = 0; i < VPT; i++) {
        e[4*i+0] = v[i].x; e[4*i+1] = v[i].y; e[4*i+2] = v[i].z; e[4*i+3] = v[i].w;
    }
#pragma unroll
    for (int j = 0; j < VPT * 4; j++) {
        bool pred = (e[j] > lb);
        unsigned b = __ballot_sync(0xffffffffu, pred);
        if (b) {   // warp-uniform: most warps skip with a single ballot
            int leader = __ffs(b) - 1;
            int cnt = __popc(b);
            int base = 0;
            if (lane == leader) base = atomicAdd(&s_n, cnt);
            base = __shfl_sync(0xffffffffu, base, leader);
            if (pred) {
                int pos = base + __popc(b & ((1u << lane) - 1u));
                if (pos < CAP) s_cand[pos] = e[j];
            }
        }
    }
    __syncthreads();
    const int n = s_n;

    if (n <= 32) {
        // ---- one-shot exact solve (warp 0): bitonic sort desc + prefix sum.
        //      Identical arithmetic to the reference on the top-n elements.
        if (warp == 0) {
            const float NEG_INF = __int_as_float(0xff800000);
            float c = (lane < n) ? s_cand[lane] : NEG_INF;
            // Bitonic sort, descending across lanes 0..31.
#pragma unroll
            for (int k = 2; k <= 32; k <<= 1) {
#pragma unroll
                for (int j = k >> 1; j > 0; j >>= 1) {
                    float o = __shfl_xor_sync(0xffffffffu, c, j);
                    bool keepMax = !((((lane & j) != 0) ^ ((lane & k) != 0)));
                    c = keepMax ? fmaxf(c, o) : fminf(c, o);
                }
            }
            // Inclusive prefix sum (lanes in descending-value order).
            float ps = c;
#pragma unroll
            for (int off = 1; off < 32; off <<= 1) {
                float o = __shfl_up_sync(0xffffffffu, ps, off);
                if (lane >= off) ps += o;
            }
            float cssv = ps - 1.0f;                     // cumsum - z
            float kf   = (float)(lane + 1);
            bool cond  = (lane < n) && (c * kf > cssv); // prefix-true pattern
            unsigned bal = __ballot_sync(0xffffffffu, cond);
            int rho = __popc(bal);                      // >= 1 always
            float tau_num = __shfl_sync(0xffffffffu, cssv, rho - 1);
            if (lane == 0) s_tau = tau_num / (float)rho;
        }
        __syncthreads();
    } else {
        // ---- fallback: block-wide Newton on registers (rare / adversarial).
        float tau = lb;
#pragma unroll 1
        for (int iter = 0; iter < 32; iter++) {
            float pssum = 0.f, pc = 0.f;
#pragma unroll
            for (int j = 0; j < VPT * 4; j++) {
                if (e[j] > tau) { pssum += e[j]; pc += 1.f; }
            }
            pssum = warp_sum(pssum);
            pc = warp_sum(pc);
            if (lane == 0) { s_red[0][warp] = pssum; s_red[1][warp] = pc; }
            __syncthreads();
            float S = 0.f, C = 0.f;
#pragma unroll
            for (int w = 0; w < NWARPS; w++) { S += s_red[0][w]; C += s_red[1][w]; }
            float ntau = (C >= 0.5f) ? (S - 1.0f) / C : tau;
            __syncthreads();
            if (ntau == tau) break;
            tau = ntau;
        }
        if (t == 0) s_tau = tau;
        __syncthreads();
    }

    const float tau = s_tau;

    // ---- epilogue: out = max(x - tau, 0), streaming stores ----
#pragma unroll
    for (int i = 0; i < VPT; i++) {
        float4 r;
        r.x = fmaxf(v[i].x - tau, 0.f);
        r.y = fmaxf(v[i].y - tau, 0.f);
        r.z = fmaxf(v[i].z - tau, 0.f);
        r.w = fmaxf(v[i].w - tau, 0.f);
        __stcs(&o4[t + i * THREADS], r);
    }
}

extern "C" void kernel_launch(void* const* d_in, const int* in_sizes, int n_in,
                              void* d_out, int out_size) {
    const float* x = (const float*)d_in[0];
    float* out = (float*)d_out;
    sparsemax_kernel<<<ROWS, THREADS>>>(x, out);
}

// round 12
// speedup vs baseline: 1.2978x; 1.2978x over previous
#include <cuda_runtime.h>

#define ROWS 4096
#define COLS 8192
#define THREADS 256
#define NWARPS (THREADS / 32)          // 8
#define VPT (COLS / (THREADS * 4))     // 8 float4 per thread = 32 floats
#define CAP 1024                       // candidate capacity

__device__ __forceinline__ float warp_sum(float v) {
#pragma unroll
    for (int off = 16; off; off >>= 1)
        v += __shfl_xor_sync(0xffffffffu, v, off);
    return v;
}
__device__ __forceinline__ float warp_max(float v) {
#pragma unroll
    for (int off = 16; off; off >>= 1)
        v = fmaxf(v, __shfl_xor_sync(0xffffffffu, v, off));
    return v;
}

__global__ void __launch_bounds__(THREADS)
sparsemax_kernel(const float* __restrict__ x, float* __restrict__ out) {
    const int row  = blockIdx.x;
    const int t    = threadIdx.x;
    const int warp = t >> 5;
    const int lane = t & 31;

    const float4* __restrict__ x4 = reinterpret_cast<const float4*>(x + (size_t)row * COLS);
    float4*       __restrict__ o4 = reinterpret_cast<float4*>(out + (size_t)row * COLS);

    __shared__ float s_max[NWARPS];
    __shared__ float s_cand[CAP];
    __shared__ int   s_n;
    __shared__ float s_tau;
    __shared__ float s_red[2][NWARPS];   // deep fallback only

    // ---- pass 1: rowmax (values NOT kept in registers -> low regcount, high occ;
    //      row stays hot in L1/L2 for the later passes, so no extra DRAM traffic) ----
    float m = __int_as_float(0xff800000);
#pragma unroll
    for (int i = 0; i < VPT; i++) {
        float4 a = x4[t + i * THREADS];
        m = fmaxf(m, fmaxf(fmaxf(a.x, a.y), fmaxf(a.z, a.w)));
    }
    m = warp_max(m);
    if (lane == 0) s_max[warp] = m;
    if (t == 0) s_n = 0;
    __syncthreads();
    float rowmax = s_max[0];
#pragma unroll
    for (int w = 1; w < NWARPS; w++) rowmax = fmaxf(rowmax, s_max[w]);

    // ---- pass 2: candidate scatter. support(tau*) subset of {x > rowmax-1}
    //      (x_max - tau <= sum_support(x - tau) = 1  =>  tau >= rowmax - 1).
    //      Re-read hits L1/L2. Predicated atomics: ~20 threads/block take them.
    const float lb = rowmax - 1.0f;
#pragma unroll
    for (int i = 0; i < VPT; i++) {
        float4 a = x4[t + i * THREADS];
        float e[4] = {a.x, a.y, a.z, a.w};
#pragma unroll
        for (int j = 0; j < 4; j++) {
            if (e[j] > lb) {
                int idx = atomicAdd(&s_n, 1);
                if (idx < CAP) s_cand[idx] = e[j];
            }
        }
    }
    __syncthreads();
    const int n = s_n;

    if (n <= 32) {
        // ---- one-shot exact solve (warp 0): bitonic desc sort + prefix sum.
        //      Identical arithmetic to the reference on the top-n elements.
        if (warp == 0) {
            const float NEG_INF = __int_as_float(0xff800000);
            float c = (lane < n) ? s_cand[lane] : NEG_INF;
#pragma unroll
            for (int k = 2; k <= 32; k <<= 1) {
#pragma unroll
                for (int j = k >> 1; j > 0; j >>= 1) {
                    float o = __shfl_xor_sync(0xffffffffu, c, j);
                    bool keepMax = !((((lane & j) != 0) ^ ((lane & k) != 0)));
                    c = keepMax ? fmaxf(c, o) : fminf(c, o);
                }
            }
            float ps = c;
#pragma unroll
            for (int off = 1; off < 32; off <<= 1) {
                float o = __shfl_up_sync(0xffffffffu, ps, off);
                if (lane >= off) ps += o;
            }
            float cssv = ps - 1.0f;                     // cumsum - z
            float kf   = (float)(lane + 1);
            bool cond  = (lane < n) && (c * kf > cssv); // prefix-true pattern
            unsigned bal = __ballot_sync(0xffffffffu, cond);
            int rho = __popc(bal);                      // >= 1 always
            float tau_num = __shfl_sync(0xffffffffu, cssv, rho - 1);
            if (lane == 0) s_tau = tau_num / (float)rho;
        }
        __syncthreads();
    } else if (n <= CAP) {
        // ---- warp-0 Newton over the candidate list (support subset of list;
        //      tau >= lb throughout, so non-candidates never contribute).
        if (warp == 0) {
            float tau = lb;
#pragma unroll 1
            for (int iter = 0; iter < 32; iter++) {
                float ps = 0.f, pc = 0.f;
                for (int idx = lane; idx < n; idx += 32) {
                    float c = s_cand[idx];
                    if (c > tau) { ps += c; pc += 1.f; }
                }
                float S = warp_sum(ps);
                float C = warp_sum(pc);
                S = __shfl_sync(0xffffffffu, S, 0);
                C = __shfl_sync(0xffffffffu, C, 0);
                float ntau = (C >= 0.5f) ? (S - 1.0f) / C : tau;
                if (ntau == tau) break;
                tau = ntau;
            }
            if (lane == 0) s_tau = tau;
        }
        __syncthreads();
    } else {
        // ---- deep fallback (adversarial only): block-wide Newton re-reading x.
        float tau = lb;
#pragma unroll 1
        for (int iter = 0; iter < 32; iter++) {
            float ps = 0.f, pc = 0.f;
#pragma unroll
            for (int i = 0; i < VPT; i++) {
                float4 a = x4[t + i * THREADS];
                if (a.x > tau) { ps += a.x; pc += 1.f; }
                if (a.y > tau) { ps += a.y; pc += 1.f; }
                if (a.z > tau) { ps += a.z; pc += 1.f; }
                if (a.w > tau) { ps += a.w; pc += 1.f; }
            }
            ps = warp_sum(ps);
            pc = warp_sum(pc);
            if (lane == 0) { s_red[0][warp] = ps; s_red[1][warp] = pc; }
            __syncthreads();
            float S = 0.f, C = 0.f;
#pragma unroll
            for (int w = 0; w < NWARPS; w++) { S += s_red[0][w]; C += s_red[1][w]; }
            float ntau = (C >= 0.5f) ? (S - 1.0f) / C : tau;
            __syncthreads();
            if (ntau == tau) break;
            tau = ntau;
        }
        if (t == 0) s_tau = tau;
        __syncthreads();
    }

    const float tau = s_tau;

    // ---- pass 3: epilogue re-read (L1/L2 hits) + streaming stores ----
#pragma unroll
    for (int i = 0; i < VPT; i++) {
        float4 a = x4[t + i * THREADS];
        float4 r;
        r.x = fmaxf(a.x - tau, 0.f);
        r.y = fmaxf(a.y - tau, 0.f);
        r.z = fmaxf(a.z - tau, 0.f);
        r.w = fmaxf(a.w - tau, 0.f);
        __stcs(&o4[t + i * THREADS], r);
    }
}

extern "C" void kernel_launch(void* const* d_in, const int* in_sizes, int n_in,
                              void* d_out, int out_size) {
    const float* x = (const float*)d_in[0];
    float* out = (float*)d_out;
    sparsemax_kernel<<<ROWS, THREADS>>>(x, out);
}